// round 16
// baseline (speedup 1.0000x reference)
#include <cuda_runtime.h>
#include <cstdint>

#define BB 64
#define NN 512
#define DD 64
#define HH 4
#define CC 64
#define NEGS 0.2f

// Scratch (device globals - no runtime allocation allowed)
__device__ float g_h[BB*HH*NN*CC];       // [b][h][n][c]  (head-major slabs)
__device__ float g_asrc[BB*HH*NN];       // [b][h][n]
__device__ float g_adst[BB*HH*NN];       // [b][h][n]
__device__ float g_part[BB*HH*NN*CC];    // per-head normalized aggregation

// ---------------------------------------------------------------------------
// k_lin (LOCKED R7 scalar mainloop; R6-style fused input combine):
// h = x @ W^T, 64x64 tile, one head per blockIdx.y, 256 threads, 4i x 4c.
// When cbp != null, x is formed on the fly: x = relu(sum_h part + cb_prev)
// (note: prep already folds the 0.25 head-mean into part).
// Epilogue: h -> g_h[b][h][n][c] slab + a_src/a_dst via shfl reduce.
// ---------------------------------------------------------------------------
__global__ __launch_bounds__(256) void k_lin(
    const float* __restrict__ x, const float* __restrict__ part,
    const float* __restrict__ W,
    const float* __restrict__ attS, const float* __restrict__ attD,
    const float* __restrict__ cbp)
{
    __shared__ float s_x[64][68];   // transposed [k][row]
    __shared__ float s_w[64][68];   // transposed [k][col]
    const int t    = threadIdx.x;
    const int row0 = blockIdx.x * 64;
    const int hh   = blockIdx.y;

    {
        const int li = t >> 2;
        const int c4 = t & 3;
        const float4* w4 = (const float4*)W;
        #pragma unroll
        for (int q = 0; q < 4; q++) {
            int kc = c4 + q * 4;
            float4 v;
            if (cbp == nullptr) {
                v = ((const float4*)x)[(row0 + li) * 16 + kc];
            } else {
                int ng = row0 + li;
                int bb = ng >> 9, n = ng & 511;
                size_t base = (((size_t)(bb * HH)) * NN + n) * CC + kc * 4;
                float4 p0 = *(const float4*)(part + base);
                float4 p1 = *(const float4*)(part + base + (size_t)NN * CC);
                float4 p2 = *(const float4*)(part + base + (size_t)2 * NN * CC);
                float4 p3 = *(const float4*)(part + base + (size_t)3 * NN * CC);
                float4 cbv = *(const float4*)(cbp + kc * 4);
                v.x = fmaxf(p0.x + p1.x + p2.x + p3.x + cbv.x, 0.f);
                v.y = fmaxf(p0.y + p1.y + p2.y + p3.y + cbv.y, 0.f);
                v.z = fmaxf(p0.z + p1.z + p2.z + p3.z + cbv.z, 0.f);
                v.w = fmaxf(p0.w + p1.w + p2.w + p3.w + cbv.w, 0.f);
            }
            s_x[kc*4+0][li] = v.x; s_x[kc*4+1][li] = v.y;
            s_x[kc*4+2][li] = v.z; s_x[kc*4+3][li] = v.w;
            float4 u = w4[(hh * 64 + li) * 16 + kc];
            s_w[kc*4+0][li] = u.x; s_w[kc*4+1][li] = u.y;
            s_w[kc*4+2][li] = u.z; s_w[kc*4+3][li] = u.w;
        }
    }
    __syncthreads();

    const int tx = t & 15, ty = t >> 4;
    float acc[4][4] = {};
    #pragma unroll
    for (int k = 0; k < 64; k++) {
        float4 a = *(const float4*)&s_x[k][ty * 4];
        float4 b = *(const float4*)&s_w[k][tx * 4];
        float av[4] = {a.x, a.y, a.z, a.w};
        float bv[4] = {b.x, b.y, b.z, b.w};
        #pragma unroll
        for (int i = 0; i < 4; i++)
            #pragma unroll
            for (int c = 0; c < 4; c++)
                acc[i][c] += av[i] * bv[c];
    }

    #pragma unroll
    for (int i = 0; i < 4; i++) {
        int ng = row0 + ty * 4 + i;
        int b = ng >> 9, n = ng & 511;
        *(float4*)&g_h[((size_t)(b * HH + hh) * NN + n) * CC + tx * 4] =
            make_float4(acc[i][0], acc[i][1], acc[i][2], acc[i][3]);
    }

    float aSv[4], aDv[4];
    #pragma unroll
    for (int c = 0; c < 4; c++) {
        aSv[c] = attS[hh * 64 + tx * 4 + c];
        aDv[c] = attD[hh * 64 + tx * 4 + c];
    }
    #pragma unroll
    for (int i = 0; i < 4; i++) {
        float ps = 0.f, pd = 0.f;
        #pragma unroll
        for (int c = 0; c < 4; c++) { ps += acc[i][c] * aSv[c]; pd += acc[i][c] * aDv[c]; }
        #pragma unroll
        for (int off = 8; off > 0; off >>= 1) {
            ps += __shfl_xor_sync(0xffffffffu, ps, off);
            pd += __shfl_xor_sync(0xffffffffu, pd, off);
        }
        if (tx == 0) {
            int ng = row0 + ty * 4 + i;
            int b = ng >> 9, n = ng & 511;
            g_asrc[(b * HH + hh) * NN + n] = ps;
            g_adst[(b * HH + hh) * NN + n] = pd;
        }
    }
}

// ---------------------------------------------------------------------------
// k_prep (R15 bucketed emission), 512 threads, one block per (b,h).
// Sort s; chunk(8) sums + scans; counting-sort i's by split k_i; during the
// per-chunk scan pass, emit part[i][c] = r1_i*S1[j][c] + r2_i*P2[j][c] for
// every i in bucket j (r includes the 0.25 head-mean factor).
// ---------------------------------------------------------------------------
extern __shared__ float psm[];

__global__ __launch_bounds__(512) void k_prep()
{
    float* s_s   = psm;              // 512
    float* s_dd  = psm + 512;        // 512
    float* s_W1  = psm + 1024;       // 512
    float* s_W2  = psm + 1536;       // 512
    int*   s_pj  = (int*)(psm + 2048);   // 512
    float* CH1   = psm + 2560;       // [66][64]
    float* CH2   = psm + 6784;       // [66][64]
    float* CH1d  = psm + 11008;      // [66]
    float* CH2d  = psm + 11074;      // [66]
    float* s1d   = psm + 11140;      // [520]
    float* p2d   = psm + 11660;      // [520]
    float* r1s   = psm + 12180;      // [512]
    float* r2s   = psm + 12692;      // [512]
    int*   s_cnt = (int*)(psm + 13204);  // [513]
    int*   scA   = (int*)(psm + 13717);  // [513]
    int*   scB   = (int*)(psm + 14230);  // [513]
    int*   s_st  = (int*)(psm + 14743);  // [513]
    int*   s_ord = (int*)(psm + 15256);  // [512] -> 15768 words total

    const int t = threadIdx.x;
    const int b = blockIdx.x;
    const int h = blockIdx.y;
    const int bh = b * HH + h;

    // phase 1: load
    s_s[t]  = g_asrc[bh * NN + t];
    s_pj[t] = t;
    s_dd[t] = g_adst[bh * NN + t];

    // phase 2: bitonic sort ascending; j<=32 stages warp-local
    {
        int prev_cross = 1;
        for (int k = 2; k <= 512; k <<= 1) {
            for (int j = k >> 1; j > 0; j >>= 1) {
                int cross = (j >= 64);
                if (cross | prev_cross) __syncthreads(); else __syncwarp();
                if (t < 256) {
                    int i = ((t & ~(j - 1)) << 1) | (t & (j - 1));
                    int p = i | j;
                    bool up = ((i & k) == 0);
                    float ki = s_s[i], kp = s_s[p];
                    if (up ? (ki > kp) : (ki < kp)) {
                        s_s[i] = kp; s_s[p] = ki;
                        int tmp = s_pj[i]; s_pj[i] = s_pj[p]; s_pj[p] = tmp;
                    }
                }
                prev_cross = cross;
            }
        }
        __syncthreads();
    }

    // phase 3: sorted weights + per-i split
    int k_reg;
    {
        float sv = s_s[t];
        s_W1[t] = __expf(sv);
        s_W2[t] = __expf(NEGS * sv);
        float thr = -s_dd[t];
        int lo = 0, hi = 512;
        while (lo < hi) {
            int mid = (lo + hi) >> 1;
            if (s_s[mid] < thr) lo = mid + 1; else hi = mid;
        }
        k_reg = lo;
    }
    __syncthreads();

    const float* hb = g_h + (size_t)bh * NN * CC;

    // phase 4: chunk sums (float2 over h rows) + scalar chunk sums
    #pragma unroll
    for (int p = t; p < 2048; p += 512) {
        int m = p >> 5, c = (p & 31) * 2;
        float2 f1 = make_float2(0.f, 0.f), f2 = make_float2(0.f, 0.f);
        #pragma unroll
        for (int r = 0; r < 8; r++) {
            int jj = m * 8 + r;
            float2 hv = *(const float2*)(hb + (size_t)s_pj[jj] * 64 + c);
            float w1 = s_W1[jj], w2 = s_W2[jj];
            f1.x += w1 * hv.x; f1.y += w1 * hv.y;
            f2.x += w2 * hv.x; f2.y += w2 * hv.y;
        }
        *(float2*)&CH1[m * 64 + c] = f1;
        *(float2*)&CH2[(m + 1) * 64 + c] = f2;
    }
    if (t < 64) {
        int m = t;
        float f1 = 0.f, f2 = 0.f;
        #pragma unroll
        for (int r = 0; r < 8; r++) { f1 += s_W1[m*8+r]; f2 += s_W2[m*8+r]; }
        CH1d[m] = f1;
        CH2d[m + 1] = f2;
    }
    __syncthreads();

    // phase 5: chunk scans
    if (t < 64) {
        const int c = t;
        CH1[64 * 64 + c] = 0.f;
        CH2[c] = 0.f;
        float run = 0.f;
        for (int m = 63; m >= 0; m--) { run += CH1[m * 64 + c]; CH1[m * 64 + c] = run; }
        float run2 = 0.f;
        for (int m = 1; m <= 64; m++) { run2 += CH2[m * 64 + c]; CH2[m * 64 + c] = run2; }
    } else if (t == 64) {
        CH1d[64] = 0.f;
        float run = 0.f;
        for (int m = 63; m >= 0; m--) { run += CH1d[m]; CH1d[m] = run; }
    } else if (t == 65) {
        CH2d[0] = 0.f;
        float run = 0.f;
        for (int m = 1; m <= 64; m++) { run += CH2d[m]; CH2d[m] = run; }
    }
    __syncthreads();

    // phase 5b: scalar full arrays (t<66) ; zero bucket counts (t>=128)
    if (t < 64) {
        int m = t;
        float run1 = CH1d[m + 1];
        #pragma unroll
        for (int r = 7; r >= 0; r--) { run1 += s_W1[m*8+r]; s1d[m*8+r] = run1; }
        float run2 = CH2d[m];
        #pragma unroll
        for (int r = 0; r < 8; r++) { p2d[m*8+r] = run2; run2 += s_W2[m*8+r]; }
    } else if (t == 64) {
        s1d[512] = 0.f; p2d[512] = CH2d[64];
    } else if (t >= 128) {
        for (int q = t - 128; q < 513; q += 384) s_cnt[q] = 0;
    }
    __syncthreads();

    // phase 5c: bucket counts
    atomicAdd(&s_cnt[k_reg], 1);
    __syncthreads();

    // phase 5d: inclusive Hillis-Steele scan of cnt (513) via ping-pong
    {
        int* pA = scA; int* pB = scB;
        for (int q = t; q < 513; q += 512) pA[q] = s_cnt[q];
        __syncthreads();
        for (int st = 1; st < 513; st <<= 1) {
            for (int q = t; q < 513; q += 512) {
                int v = pA[q];
                if (q >= st) v += pA[q - st];
                pB[q] = v;
            }
            __syncthreads();
            int* tmp = pA; pA = pB; pB = tmp;
        }
        for (int q = t; q < 513; q += 512) {
            int ex = pA[q] - s_cnt[q];
            s_st[q] = ex;
            pB[q]   = ex;
        }
        __syncthreads();
        int pos = atomicAdd(&pB[k_reg], 1);
        s_ord[pos] = t;
        float dv = s_dd[t];
        float e1 = __expf(dv);
        float e2 = __expf(NEGS * dv);
        float den = e1 * s1d[k_reg] + e2 * p2d[k_reg];
        float inv = 0.25f * __frcp_rn(den);
        r1s[t] = e1 * inv;
        r2s[t] = e2 * inv;
    }
    __syncthreads();

    // phase 6: scan sweep with fused bucket emission
    float* gp = g_part + (size_t)bh * NN * CC;
    #pragma unroll
    for (int p = t; p < 2048; p += 512) {
        int m = p >> 5, c = (p & 31) * 2;
        float2 hv[8];
        #pragma unroll
        for (int r = 0; r < 8; r++)
            hv[r] = *(const float2*)(hb + (size_t)s_pj[m * 8 + r] * 64 + c);
        float2 p2r[8];
        float2 run2 = *(const float2*)&CH2[m * 64 + c];
        #pragma unroll
        for (int r = 0; r < 8; r++) {
            p2r[r] = run2;
            float w = s_W2[m * 8 + r];
            run2.x += w * hv[r].x; run2.y += w * hv[r].y;
        }
        float2 run1 = *(const float2*)&CH1[(m + 1) * 64 + c];
        #pragma unroll
        for (int r = 7; r >= 0; r--) {
            int j = m * 8 + r;
            float w = s_W1[j];
            run1.x += w * hv[r].x; run1.y += w * hv[r].y;
            int st0 = s_st[j], en = st0 + s_cnt[j];
            for (int pp = st0; pp < en; pp++) {
                int i = s_ord[pp];
                float r1v = r1s[i], r2v = r2s[i];
                float2 o;
                o.x = r1v * run1.x + r2v * p2r[r].x;
                o.y = r1v * run1.y + r2v * p2r[r].y;
                *(float2*)&gp[(size_t)i * 64 + c] = o;
            }
        }
    }
    // bucket 512 (k_i == 512): S1 = 0, P2 = total prefix
    {
        int n512 = s_cnt[512], base = s_st[512];
        for (int q = t; q < n512 * 32; q += 512) {
            int e = q >> 5, c = (q & 31) * 2;
            int i = s_ord[base + e];
            float r2v = r2s[i];
            float2 o;
            o.x = r2v * CH2[64 * 64 + c];
            o.y = r2v * CH2[64 * 64 + c + 1];
            *(float2*)&gp[(size_t)i * 64 + c] = o;
        }
    }
}

// ---------------------------------------------------------------------------
// k_read_comb: head-combine + bias + relu + node-mean pooling + readout.
// ---------------------------------------------------------------------------
__global__ __launch_bounds__(256) void k_read_comb(
    const float* __restrict__ rw, const float* __restrict__ rb,
    const float* __restrict__ cb2, float* __restrict__ out)
{
    __shared__ float s_part[4][64];
    __shared__ float s_pool[64];
    const int t = threadIdx.x;
    const int b = blockIdx.x;
    const int c = t & 63, pg = t >> 6;
    const float bias = cb2[c];
    float s = 0.f;
    for (int i = pg; i < NN; i += 4) {
        size_t base = ((size_t)(b * HH) * NN + i) * CC + c;
        float v = g_part[base] + g_part[base + (size_t)NN * CC]
                + g_part[base + (size_t)2 * NN * CC]
                + g_part[base + (size_t)3 * NN * CC];
        s += fmaxf(v + bias, 0.f);
    }
    s_part[pg][c] = s;
    __syncthreads();
    if (t < 64)
        s_pool[t] = (s_part[0][t] + s_part[1][t] + s_part[2][t] + s_part[3][t])
                    * (1.0f / NN);
    __syncthreads();
    if (t < 64) {
        float a = rb[t];
        #pragma unroll 8
        for (int c2 = 0; c2 < 64; c2++)
            a += s_pool[c2] * rw[t * 64 + c2];
        out[b * 64 + t] = a;
    }
}

// ---------------------------------------------------------------------------
extern "C" void kernel_launch(void* const* d_in, const int* in_sizes, int n_in,
                              void* d_out, int out_size)
{
    const float* emb = (const float*)d_in[0];
    const float* lin = (const float*)d_in[1];
    const float* aS  = (const float*)d_in[2];
    const float* aD  = (const float*)d_in[3];
    const float* cb  = (const float*)d_in[4];
    const float* rw  = (const float*)d_in[5];
    const float* rb  = (const float*)d_in[6];
    float* out = (float*)d_out;

    float* gpart = nullptr;
    cudaGetSymbolAddress((void**)&gpart, g_part);

    const int PREP_SMEM = 15768 * 4;   // 63072 B
    cudaFuncSetAttribute(k_prep, cudaFuncAttributeMaxDynamicSharedMemorySize, PREP_SMEM);

    for (int l = 0; l < 3; l++) {
        const float* cbp = (l == 0) ? nullptr : (cb + (l - 1) * CC);
        k_lin<<<dim3(512, 4), 256>>>(emb, gpart, lin + l * 16384,
                                     aS + l * HH * CC, aD + l * HH * CC, cbp);
        k_prep<<<dim3(64, 4), 512, PREP_SMEM>>>();
    }
    k_read_comb<<<64, 256>>>(rw, rb, cb + 2 * CC, out);
}